// round 16
// baseline (speedup 1.0000x reference)
#include <cuda_runtime.h>
#include <cuda_bf16.h>
#include <math.h>
#include <stdint.h>

#define WOUT 40
#define HWOUT 1600
#define CIN 256
#define BATCH 4

#define BN 64
#define KC 64
#define NTHREADS 1024
#define GRID 100
#define KDEF (CIN*16)
#define KCONV (CIN*9)

#define ND (256*KDEF)
#define NCOM (64*KCONV)
#define NRES (256*KCONV)

// smem (bytes): A [0,131072) B [131072,163840) OM [163840,176128) MBAR [176128,176192)
#define OFF_OM 163840
#define OFF_MBAR 176128
#define SMEM_TOTAL 176192

__device__ float g_f[BATCH*CIN*HWOUT];
// weights stored as pre-swizzled smem images, chunk-major (c*2+fmt)*ABUF blocks
__device__ __align__(16) __nv_bfloat16 g_wdef[2*2*ND];
__device__ __align__(16) __nv_bfloat16 g_wcom[2*2*NCOM];
__device__ __align__(16) __nv_bfloat16 g_wres[2*NRES];
__device__ unsigned int g_cnt[8];

__device__ __forceinline__ uint32_t smem_u32(const void* p) {
    uint32_t a;
    asm("{ .reg .u64 t; cvta.to.shared.u64 t, %1; cvt.u32.u64 %0, t; }" : "=r"(a) : "l"(p));
    return a;
}
__device__ __forceinline__ uint32_t sw128(uint32_t o) { return o ^ ((o >> 3) & 0x70); }

__device__ __forceinline__ void ldsm4(uint32_t* r, uint32_t addr) {
    asm volatile("ldmatrix.sync.aligned.m8n8.x4.shared.b16 {%0,%1,%2,%3}, [%4];"
        : "=r"(r[0]), "=r"(r[1]), "=r"(r[2]), "=r"(r[3]) : "r"(addr));
}
__device__ __forceinline__ void ldsm2(uint32_t* r, uint32_t addr) {
    asm volatile("ldmatrix.sync.aligned.m8n8.x2.shared.b16 {%0,%1}, [%2];"
        : "=r"(r[0]), "=r"(r[1]) : "r"(addr));
}
__device__ __forceinline__ void mma16816(float* c, const uint32_t* a, uint32_t b0, uint32_t b1) {
    asm volatile("mma.sync.aligned.m16n8k16.row.col.f32.bf16.bf16.f32 "
        "{%0,%1,%2,%3},{%4,%5,%6,%7},{%8,%9},{%0,%1,%2,%3};"
        : "+f"(c[0]), "+f"(c[1]), "+f"(c[2]), "+f"(c[3])
        : "r"(a[0]), "r"(a[1]), "r"(a[2]), "r"(a[3]), "r"(b0), "r"(b1));
}

#define MBAR_INIT(a, n) asm volatile("mbarrier.init.shared.b64 [%0], %1;" :: "r"(a), "r"(n) : "memory")
#define MBAR_EXPECT_TX(a, bytes) \
    asm volatile("mbarrier.arrive.expect_tx.shared.b64 _, [%0], %1;" :: "r"(a), "r"(bytes) : "memory")
#define BULK_G2S(dst, src, size, mbar) \
    asm volatile("cp.async.bulk.shared::cta.global.mbarrier::complete_tx::bytes [%0], [%1], %2, [%3];" \
        :: "r"(dst), "l"(src), "r"(size), "r"(mbar) : "memory")
#define MBAR_WAIT(addr, par) do { \
    uint32_t _m = (addr); uint32_t _p = (uint32_t)(par); uint32_t _d; \
    asm volatile("{\n\t.reg .pred p;\n\tmbarrier.try_wait.parity.acquire.cta.shared::cta.b64 p, [%1], %2;\n\tselp.b32 %0, 1, 0, p;\n\t}" \
        : "=r"(_d) : "r"(_m), "r"(_p) : "memory"); \
    if (!_d) { \
        asm volatile("{\n\t.reg .pred P1;\n\tWL_%=:\n\tmbarrier.try_wait.parity.acquire.cta.shared::cta.b64 P1, [%0], %1, 0x989680;\n\t@P1 bra.uni WD_%=;\n\tbra.uni WL_%=;\n\tWD_%=:\n\t}" \
            :: "r"(_m), "r"(_p) : "memory"); } \
} while(0)

// monotone-counter grid barrier (graph-replay safe)
__device__ __forceinline__ void grid_bar(int slot) {
    __syncthreads();
    if (threadIdx.x == 0) {
        __threadfence();
        unsigned int old = atomicAdd(&g_cnt[slot], 1u);
        unsigned int target = (old / GRID) * GRID + GRID;
        while (*(volatile unsigned int*)&g_cnt[slot] < target) __nanosleep(64);
    }
    __syncthreads();
}

// MODE 0: implicit 3x3 conv (s1 p1; x = mutable gf, read via __ldcg).
// MODE 1: modulated deform conv (k=4,K=16), meta from smem om; x = immutable feat.
// EPI 0:+bias 1:relu(v+b)+__ldcg(epi) 2:v+b+__ldcg(epi) 3:+bias->som
// 32 warps. MT=4: wm 8x32rows, wn 4x16cols. MT=1: wm 4x16rows, wn 8x8cols.
template<int MODE, int EPI, int MT>
__device__ void stage_gemm(char* smem, int bx,
        const float* __restrict__ x, int Hin, int Win,
        const char* __restrict__ wblk, const float* __restrict__ bias,
        float* som, const float* __restrict__ epi_src, float* __restrict__ out,
        int Cout, int Ktot, int stride, int pad, int dil, int* ph)
{
    constexpr int BM = MT * 64;
    constexpr int ABUF = BM * 128;
    constexpr int OFF_B = 4 * ABUF;
    constexpr int MI = (MT == 4) ? 2 : 1;
    constexpr int JN = (MT == 4) ? 2 : 1;

    const uint32_t sb = smem_u32(smem);
    const int tid = threadIdx.x;
    const int wid = tid >> 5, lid = tid & 31;
    const int n0 = bx * BN;
    const int b  = n0 / HWOUT;
    const int hw0 = n0 - b * HWOUT;
    const int HWin = Hin * Win;
    const float* xb = x + (size_t)b * CIN * HWin;

    __syncthreads();   // previous stage fully done with smem

    const int pxT = tid & 63;
    const int tap = tid >> 6;            // 0..15
    const uint32_t xorv = (uint32_t)((pxT & 7) << 4);
    const uint32_t rowb = (uint32_t)(pxT * 128);

    // ---- per-thread deform meta (ONE tap) from smem om ----
    int2 ad; float4 wq;
    if (MODE == 1) {
        int hw = hw0 + pxT;
        int h = hw / WOUT, w = hw - h * WOUT;
        float dy = som[(2*tap  ) * 64 + pxT];
        float dx = som[(2*tap+1) * 64 + pxT];
        float mm = som[(32+tap ) * 64 + pxT];
        mm = 1.0f / (1.0f + expf(-mm));
        float py = (float)((tap >> 2) * dil + h * stride - pad) + dy;
        float px = (float)((tap &  3) * dil + w * stride - pad) + dx;
        float fy = floorf(py), fx = floorf(px);
        int y0 = (int)fy, x0 = (int)fx;
        int y1 = y0 + 1, x1 = x0 + 1;
        float ly = py - fy, lx = px - fx;
        float wy0 = ((y0 >= 0) & (y0 < Hin)) ? (1.f - ly) * mm : 0.f;
        float wy1 = ((y1 >= 0) & (y1 < Hin)) ? ly * mm : 0.f;
        float wx0 = ((x0 >= 0) & (x0 < Win)) ? (1.f - lx) : 0.f;
        float wx1 = ((x1 >= 0) & (x1 < Win)) ? lx : 0.f;
        int xL = min(max(x0, 0), Win - 2);
        float wL = (x0 == xL ? wx0 : 0.f) + (x1 == xL ? wx1 : 0.f);
        float wR = (x0 == xL + 1 ? wx0 : 0.f) + (x1 == xL + 1 ? wx1 : 0.f);
        int yT = min(max(y0, 0), Hin - 1);
        int yB = min(max(y1, 0), Hin - 1);
        ad = make_int2(yT * Win + xL, (yB - yT) * Win);
        wq = make_float4(wy0 * wL, wy0 * wR, wy1 * wL, wy1 * wR);
    }

    float acc[MI][JN][4];
#pragma unroll
    for (int i = 0; i < MI; i++)
#pragma unroll
        for (int j = 0; j < JN; j++)
#pragma unroll
            for (int q = 0; q < 4; q++) acc[i][j][q] = 0.f;

    const int NC = Ktot / KC;
    const int wm = (MT == 4) ? (wid & 7) : (wid & 3);
    const int wn = (MT == 4) ? (wid >> 3) : (wid >> 2);
    const int m0w = wm * ((MT == 4) ? 32 : 16);
    const int n0w = wn * ((MT == 4) ? 16 : 8);

    // ---- A tile: 2 bulk copies of the pre-swizzled image (1 thread) ----
    auto loadA_bulk = [&](int c, int buf) {
        if (tid == 0) {
            uint32_t mb = sb + OFF_MBAR + buf * 8;
            asm volatile("fence.proxy.async.shared::cta;" ::: "memory");
            MBAR_EXPECT_TX(mb, (uint32_t)(2 * ABUF));
            BULK_G2S(sb + (uint32_t)((buf*2 + 0) * ABUF),
                     wblk + (size_t)(c*2 + 0) * ABUF, (uint32_t)ABUF, mb);
            BULK_G2S(sb + (uint32_t)((buf*2 + 1) * ABUF),
                     wblk + (size_t)(c*2 + 1) * ABUF, (uint32_t)ABUF, mb);
        }
    };
    auto waitA = [&](int buf) {
        uint32_t mb = sb + OFF_MBAR + buf * 8;
        MBAR_WAIT(mb, ph[buf]);
        ph[buf] ^= 1;
    };

    // ---- deform gather: per (chunk, channel q): 4 corner LDG for this thread's tap ----
    auto ldg_q = [&](int c, int q, float* r4) {
        const float* p = xb + (size_t)(c * 4 + q) * HWin + ad.x;
        r4[0] = p[0];
        r4[1] = p[1];
        r4[2] = p[ad.y];
        r4[3] = p[ad.y + 1];
    };
    auto sts_q = [&](int q, int buf, const float* r4) {
        float v = wq.x*r4[0] + wq.y*r4[1] + wq.z*r4[2] + wq.w*r4[3];
        __nv_bfloat16 hbf = __float2bfloat16(v);
        __nv_bfloat16 lbf = __float2bfloat16(v - __bfloat162float(hbf));
        uint32_t so = rowb + (((uint32_t)(q * 32 + tap * 2)) ^ xorv);
        *(__nv_bfloat16*)(smem + OFF_B + (buf*2 + 0) * 8192 + so) = hbf;
        *(__nv_bfloat16*)(smem + OFF_B + (buf*2 + 1) * 8192 + so) = lbf;
    };

    // ---- conv gather: 4 k-values per thread ----
    auto ldg_conv = [&](int c, float* r4) {
        int hw = hw0 + pxT;
        int h = hw / WOUT, w_ = hw - h * WOUT;
        int k0 = c * KC + tap * 4;
#pragma unroll
        for (int t = 0; t < 4; t++) {
            int k = k0 + t;
            int ci = k / 9, jj = k - ci * 9;
            int y  = h + jj / 3 - 1;
            int xx = w_ + (jj - (jj / 3) * 3) - 1;
            r4[t] = (y >= 0 && y < Hin && xx >= 0 && xx < Win)
                 ? __ldcg(&xb[(size_t)ci * HWin + y * Win + xx]) : 0.f;
        }
    };
    auto sts_conv = [&](int buf, const float* r4, int half) {
        __nv_bfloat162 hh = __floats2bfloat162_rn(r4[half*2], r4[half*2+1]);
        float l0 = r4[half*2]   - __bfloat162float(hh.x);
        float l1 = r4[half*2+1] - __bfloat162float(hh.y);
        __nv_bfloat162 ll = __floats2bfloat162_rn(l0, l1);
        uint32_t so = rowb + (((uint32_t)(tap * 8 + half * 4)) ^ xorv);
        *(uint32_t*)(smem + OFF_B + (buf*2 + 0) * 8192 + so) = *(uint32_t*)&hh;
        *(uint32_t*)(smem + OFF_B + (buf*2 + 1) * 8192 + so) = *(uint32_t*)&ll;
    };

    const uint32_t aOff = (uint32_t)((m0w + (lid & 15)) * 128 + (lid >> 4) * 16);
    const uint32_t bOff4 = (uint32_t)((n0w + (lid & 7) + ((lid >> 4) & 1) * 8) * 128 + ((lid >> 3) & 1) * 16);
    const uint32_t bOff2 = (uint32_t)((n0w + (lid & 7)) * 128 + ((lid >> 3) & 1) * 16);

    auto mma_ks = [&](int buf, int ks) {
        const uint32_t sAh = sb + (uint32_t)((buf*2 + 0) * ABUF);
        const uint32_t sAl = sb + (uint32_t)((buf*2 + 1) * ABUF);
        const uint32_t sBh = sb + OFF_B + (buf*2 + 0) * 8192;
        const uint32_t sBl = sb + OFF_B + (buf*2 + 1) * 8192;
        if (MT == 4) {
            uint32_t bh[4], bl[4];
            ldsm4(bh, sBh + sw128(bOff4 + (uint32_t)(ks * 32)));
            ldsm4(bl, sBl + sw128(bOff4 + (uint32_t)(ks * 32)));
#pragma unroll
            for (int i = 0; i < MI; i++) {
                uint32_t ah[4], al[4];
                ldsm4(ah, sAh + sw128(aOff + (uint32_t)(i * 2048 + ks * 32)));
                ldsm4(al, sAl + sw128(aOff + (uint32_t)(i * 2048 + ks * 32)));
#pragma unroll
                for (int jn = 0; jn < JN; jn++) {
                    int sel = jn * 2;
                    mma16816(acc[i][jn], ah, bh[sel], bh[sel + 1]);
                    mma16816(acc[i][jn], ah, bl[sel], bl[sel + 1]);
                    mma16816(acc[i][jn], al, bh[sel], bh[sel + 1]);
                }
            }
        } else {
            uint32_t bh[2], bl[2], ah[4], al[4];
            ldsm2(bh, sBh + sw128(bOff2 + (uint32_t)(ks * 32)));
            ldsm2(bl, sBl + sw128(bOff2 + (uint32_t)(ks * 32)));
            ldsm4(ah, sAh + sw128(aOff + (uint32_t)(ks * 32)));
            ldsm4(al, sAl + sw128(aOff + (uint32_t)(ks * 32)));
            mma16816(acc[0][0], ah, bh[0], bh[1]);
            mma16816(acc[0][0], ah, bl[0], bl[1]);
            mma16816(acc[0][0], al, bh[0], bh[1]);
        }
    };

    // ---- prologue: chunk 0 ----
    loadA_bulk(0, 0);
    if (MODE == 1) {
        float r4[4];
#pragma unroll
        for (int q = 0; q < 4; q++) { ldg_q(0, q, r4); sts_q(q, 0, r4); }
    } else {
        float r4[4];
        ldg_conv(0, r4);
        sts_conv(0, r4, 0);
        sts_conv(0, r4, 1);
    }
    waitA(0);
    __syncthreads();

    // ---- mainloop ----
    if (MODE == 1) {
        float rA[4], rB[4];
        for (int c = 0; c < NC; c++) {
            const int buf = c & 1;
            const bool nxt = (c + 1 < NC);
            if (nxt) {
                loadA_bulk(c + 1, buf ^ 1);
                ldg_q(c + 1, 0, rA);
                ldg_q(c + 1, 1, rB);
            }
            mma_ks(buf, 0);
            if (nxt) { sts_q(0, buf ^ 1, rA); ldg_q(c + 1, 2, rA); }
            mma_ks(buf, 1);
            if (nxt) { sts_q(1, buf ^ 1, rB); ldg_q(c + 1, 3, rB); }
            mma_ks(buf, 2);
            if (nxt) sts_q(2, buf ^ 1, rA);
            mma_ks(buf, 3);
            if (nxt) {
                sts_q(3, buf ^ 1, rB);
                waitA(buf ^ 1);
            }
            __syncthreads();
        }
    } else {
        float r4[4];
        for (int c = 0; c < NC; c++) {
            const int buf = c & 1;
            const bool nxt = (c + 1 < NC);
            if (nxt) {
                loadA_bulk(c + 1, buf ^ 1);
                ldg_conv(c + 1, r4);
            }
            mma_ks(buf, 0);
            mma_ks(buf, 1);
            if (nxt) sts_conv(buf ^ 1, r4, 0);
            mma_ks(buf, 2);
            mma_ks(buf, 3);
            if (nxt) {
                sts_conv(buf ^ 1, r4, 1);
                waitA(buf ^ 1);
            }
            __syncthreads();
        }
    }

    // ---- epilogue ----
#pragma unroll
    for (int i = 0; i < MI; i++) {
        int row0 = m0w + i * 16 + (lid >> 2);
#pragma unroll
        for (int half = 0; half < 2; half++) {
            int co = row0 + half * 8;
            if (co >= Cout) continue;
            float bv = bias[co];
#pragma unroll
            for (int jn = 0; jn < JN; jn++) {
                float v0 = acc[i][jn][half * 2 + 0] + bv;
                float v1 = acc[i][jn][half * 2 + 1] + bv;
                if (EPI == 3) {
                    int cb = co * 64 + n0w + (lid & 3) * 2 + jn * 8;
                    som[cb] = v0; som[cb + 1] = v1;
                } else {
                    size_t o = ((size_t)b * Cout + co) * HWOUT + hw0 + n0w + (lid & 3) * 2 + jn * 8;
                    if (EPI == 1) {
                        float2 s = __ldcg((const float2*)(epi_src + o));
                        v0 = fmaxf(v0, 0.f) + s.x; v1 = fmaxf(v1, 0.f) + s.y;
                    } else if (EPI == 2) {
                        float2 s = __ldcg((const float2*)(epi_src + o));
                        v0 += s.x; v1 += s.y;
                    }
                    *(float2*)(out + o) = make_float2(v0, v1);
                }
            }
        }
    }
}

__global__ void __launch_bounds__(NTHREADS)
dcnfpn_persist(const float* __restrict__ f0, const float* __restrict__ f1,
               const float* __restrict__ f2,
               const float* cw0, const float* cb0, const float* cw1, const float* cb1,
               const float* dw0, const float* db0, const float* dw1, const float* db1,
               const float* rw, const float* rb, float* __restrict__ out)
{
    extern __shared__ __align__(1024) char smem[];
    const int bx = blockIdx.x;
    const int tid = threadIdx.x;
    const int gtid = bx * NTHREADS + tid;
    const int GT = GRID * NTHREADS;
    const uint32_t sb = smem_u32(smem);

    if (tid == 0) {
        MBAR_INIT(sb + OFF_MBAR, 1);
        MBAR_INIT(sb + OFF_MBAR + 8, 1);
    }

    // ---- prep: weights fp32 -> bf16 hi/lo into pre-swizzled smem images ----
    {
        const float* dsrc[2] = {dw0, dw1};
        for (int l = 0; l < 2; l++) {
            char* base = (char*)g_wdef + (size_t)l * 2 * ND * 2;
            for (int i = gtid; i < ND; i += GT) {
                int r = i >> 12, k = i & 4095;
                int c = k >> 6, j = (k >> 3) & 7, t = k & 7;
                float v = dsrc[l][i];
                __nv_bfloat16 hbf = __float2bfloat16(v);
                __nv_bfloat16 lbf = __float2bfloat16(v - __bfloat162float(hbf));
                uint32_t off = (uint32_t)((c * 2) * 32768) + sw128((uint32_t)(r*128 + j*16)) + t*2;
                *(__nv_bfloat16*)(base + off)         = hbf;
                *(__nv_bfloat16*)(base + off + 32768) = lbf;
            }
        }
        const float* csrc[2] = {cw0, cw1};
        for (int l = 0; l < 2; l++) {
            char* base = (char*)g_wcom + (size_t)l * 2 * NCOM * 2;
            for (int i = gtid; i < NCOM; i += GT) {
                int r = i / KCONV, k = i - r * KCONV;
                int c = k >> 6, j = (k >> 3) & 7, t = k & 7;
                float v = (r < 48) ? csrc[l][i] : 0.f;
                __nv_bfloat16 hbf = __float2bfloat16(v);
                __nv_bfloat16 lbf = __float2bfloat16(v - __bfloat162float(hbf));
                uint32_t off = (uint32_t)((c * 2) * 8192) + sw128((uint32_t)(r*128 + j*16)) + t*2;
                *(__nv_bfloat16*)(base + off)        = hbf;
                *(__nv_bfloat16*)(base + off + 8192) = lbf;
            }
        }
        {
            char* base = (char*)g_wres;
            for (int i = gtid; i < NRES; i += GT) {
                int r = i / KCONV, k = i - r * KCONV;
                int c = k >> 6, j = (k >> 3) & 7, t = k & 7;
                float v = rw[i];
                __nv_bfloat16 hbf = __float2bfloat16(v);
                __nv_bfloat16 lbf = __float2bfloat16(v - __bfloat162float(hbf));
                uint32_t off = (uint32_t)((c * 2) * 32768) + sw128((uint32_t)(r*128 + j*16)) + t*2;
                *(__nv_bfloat16*)(base + off)         = hbf;
                *(__nv_bfloat16*)(base + off + 32768) = lbf;
            }
        }
        const float4* s4 = (const float4*)f2;
        float4* d4 = (float4*)g_f;
        for (int i = gtid; i < BATCH*CIN*HWOUT/4; i += GT) d4[i] = s4[i];
    }
    grid_bar(0);

    float* som = (float*)(smem + OFF_OM);
    const float* feats[2] = {f1, f0};
    const float* cb[2] = {cb0, cb1};
    const float* db[2] = {db0, db1};
    const int Hins[2] = {80, 160};
    const int strides[2] = {2, 4};
    const int pads[2] = {1, 3};
    const int dils[2] = {1, 3};
    int ph[2] = {0, 0};

    int slot = 1;
    for (int rep = 0; rep < 2; rep++) {
        for (int l = 0; l < 2; l++) {
            stage_gemm<0,3,1>(smem, bx, g_f, 40, 40,
                (const char*)g_wcom + (size_t)l*2*NCOM*2,
                cb[l], som, nullptr, nullptr, 48, KCONV, 1, 1, 1, ph);
            stage_gemm<1,1,4>(smem, bx, feats[l], Hins[l], Hins[l],
                (const char*)g_wdef + (size_t)l*2*ND*2,
                db[l], som, g_f, g_f, 256, KDEF, strides[l], pads[l], dils[l], ph);
            grid_bar(slot++);
        }
    }
    stage_gemm<0,2,4>(smem, bx, g_f, 40, 40,
        (const char*)g_wres, rb, nullptr, f2, out, 256, KCONV, 1, 1, 1, ph);
}

extern "C" void kernel_launch(void* const* d_in, const int* in_sizes, int n_in,
                              void* d_out, int out_size)
{
    const float* f0 = (const float*)d_in[0];
    const float* f1 = (const float*)d_in[1];
    const float* f2 = (const float*)d_in[2];

    cudaFuncSetAttribute(dcnfpn_persist, cudaFuncAttributeMaxDynamicSharedMemorySize, SMEM_TOTAL);

    dcnfpn_persist<<<GRID, NTHREADS, SMEM_TOTAL>>>(
        f0, f1, f2,
        (const float*)d_in[3], (const float*)d_in[4],
        (const float*)d_in[5], (const float*)d_in[6],
        (const float*)d_in[7], (const float*)d_in[8],
        (const float*)d_in[9], (const float*)d_in[10],
        (const float*)d_in[11], (const float*)d_in[12],
        (float*)d_out);
}

// round 17
// speedup vs baseline: 1.0851x; 1.0851x over previous
#include <cuda_runtime.h>
#include <cuda_bf16.h>
#include <math.h>
#include <stdint.h>

#define WOUT 40
#define HWOUT 1600
#define CIN 256
#define BATCH 4

#define BN 64
#define KC 64
#define NTHREADS 512
#define GRID 100
#define KDEF (CIN*16)
#define KCONV (CIN*9)

#define ND (256*KDEF)
#define NCOM (64*KCONV)
#define NRES (256*KCONV)

// smem (bytes): A [0, 4*ABUF) (max 131072) | B: OFF_B=4*ABUF, 8 x 8192
// OM fixed [196608,208896) | MBAR fixed [208896,208992)
#define OFF_OM 196608
#define OFF_MBAR 208896
#define SMEM_TOTAL 209024

__device__ float g_f[BATCH*CIN*HWOUT];
// weights as pre-swizzled smem images, chunk-major (c*2+fmt)*ABUF blocks
__device__ __align__(16) __nv_bfloat16 g_wdef[2*2*ND];
__device__ __align__(16) __nv_bfloat16 g_wcom[2*2*NCOM];
__device__ __align__(16) __nv_bfloat16 g_wres[2*NRES];
__device__ unsigned int g_cnt[8];

__device__ __forceinline__ uint32_t smem_u32(const void* p) {
    uint32_t a;
    asm("{ .reg .u64 t; cvta.to.shared.u64 t, %1; cvt.u32.u64 %0, t; }" : "=r"(a) : "l"(p));
    return a;
}
__device__ __forceinline__ uint32_t sw128(uint32_t o) { return o ^ ((o >> 3) & 0x70); }

__device__ __forceinline__ void ldsm4(uint32_t* r, uint32_t addr) {
    asm volatile("ldmatrix.sync.aligned.m8n8.x4.shared.b16 {%0,%1,%2,%3}, [%4];"
        : "=r"(r[0]), "=r"(r[1]), "=r"(r[2]), "=r"(r[3]) : "r"(addr));
}
__device__ __forceinline__ void mma16816(float* c, const uint32_t* a, uint32_t b0, uint32_t b1) {
    asm volatile("mma.sync.aligned.m16n8k16.row.col.f32.bf16.bf16.f32 "
        "{%0,%1,%2,%3},{%4,%5,%6,%7},{%8,%9},{%0,%1,%2,%3};"
        : "+f"(c[0]), "+f"(c[1]), "+f"(c[2]), "+f"(c[3])
        : "r"(a[0]), "r"(a[1]), "r"(a[2]), "r"(a[3]), "r"(b0), "r"(b1));
}

#define MBAR_INIT(a, n) asm volatile("mbarrier.init.shared.b64 [%0], %1;" :: "r"(a), "r"(n) : "memory")
#define MBAR_ARRIVE(a)  asm volatile("mbarrier.arrive.shared.b64 _, [%0];" :: "r"(a) : "memory")
#define MBAR_EXPECT_TX(a, bytes) \
    asm volatile("mbarrier.arrive.expect_tx.shared.b64 _, [%0], %1;" :: "r"(a), "r"(bytes) : "memory")
#define BULK_G2S(dst, src, size, mbar) \
    asm volatile("cp.async.bulk.shared::cta.global.mbarrier::complete_tx::bytes [%0], [%1], %2, [%3];" \
        :: "r"(dst), "l"(src), "r"(size), "r"(mbar) : "memory")
#define MBAR_WAIT(addr, par) do { \
    uint32_t _m = (addr); uint32_t _p = (uint32_t)(par); uint32_t _d; \
    asm volatile("{\n\t.reg .pred p;\n\tmbarrier.try_wait.parity.acquire.cta.shared::cta.b64 p, [%1], %2;\n\tselp.b32 %0, 1, 0, p;\n\t}" \
        : "=r"(_d) : "r"(_m), "r"(_p) : "memory"); \
    if (!_d) { \
        asm volatile("{\n\t.reg .pred P1;\n\tWL_%=:\n\tmbarrier.try_wait.parity.acquire.cta.shared::cta.b64 P1, [%0], %1, 0x989680;\n\t@P1 bra.uni WD_%=;\n\tbra.uni WL_%=;\n\tWD_%=:\n\t}" \
            :: "r"(_m), "r"(_p) : "memory"); } \
} while(0)

// monotone-counter grid barrier (graph-replay safe)
__device__ __forceinline__ void grid_bar(int slot) {
    __syncthreads();
    if (threadIdx.x == 0) {
        __threadfence();
        unsigned int old = atomicAdd(&g_cnt[slot], 1u);
        unsigned int target = (old / GRID) * GRID + GRID;
        while (*(volatile unsigned int*)&g_cnt[slot] < target) __nanosleep(64);
    }
    __syncthreads();
}

// Warp-specialized stage: warps 0-7 consume (MMA), warps 8-15 produce (gather).
// MODE 0: implicit 3x3 conv (s1 p1; x mutable -> __ldcg). MODE 1: deform conv, meta from som.
// EPI 0:+bias 1:relu(v+b)+__ldcg(epi) 2:v+b+__ldcg(epi) 3:+bias->som
template<int MODE, int EPI, int MT>
__device__ void stage_gemm(char* smem, int bx,
        const float* __restrict__ x, int Hin, int Win,
        const char* __restrict__ wblk, const float* __restrict__ bias,
        float* som, const float* __restrict__ epi_src, float* __restrict__ out,
        int Cout, int Ktot, int stride, int pad, int dil,
        uint32_t* phF, uint32_t* phE, uint32_t* phA)
{
    constexpr int BM = MT * 64;
    constexpr int ABUF = BM * 128;
    constexpr int OFF_B = 4 * ABUF;

    const uint32_t sb = smem_u32(smem);
    const int tid = threadIdx.x;
    const int n0 = bx * BN;
    const int b  = n0 / HWOUT;
    const int hw0 = n0 - b * HWOUT;
    const int HWin = Hin * Win;
    const float* xb = x + (size_t)b * CIN * HWin;
    const int NC = Ktot / KC;

    __syncthreads();   // previous stage fully done with smem (incl. som)

    if (tid >= 256) {
        // ================= PRODUCER (warps 8-15) =================
        const int pt = tid - 256;
        const int pxT = pt & 63;
        const int g = pt >> 6;                 // 0..3
        const uint32_t xorv = (uint32_t)((pxT & 7) << 4);
        const uint32_t rowb = (uint32_t)(pxT * 128);

        if (MODE == 1) {
            // meta for tap-pairs {g, g+4} -> taps {2p, 2p+1}
            int2 ad[2][2]; float4 wq[2][2];
#pragma unroll
            for (int pp = 0; pp < 2; pp++) {
                int pairIdx = g + pp * 4;
#pragma unroll
                for (int u = 0; u < 2; u++) {
                    int k = pairIdx * 2 + u;
                    int hw = hw0 + pxT;
                    int h = hw / WOUT, w = hw - h * WOUT;
                    float dy = som[(2*k  ) * 64 + pxT];
                    float dx = som[(2*k+1) * 64 + pxT];
                    float mm = som[(32+k ) * 64 + pxT];
                    mm = 1.0f / (1.0f + expf(-mm));
                    float py = (float)((k >> 2) * dil + h * stride - pad) + dy;
                    float px = (float)((k &  3) * dil + w * stride - pad) + dx;
                    float fy = floorf(py), fx = floorf(px);
                    int y0 = (int)fy, x0 = (int)fx;
                    int y1 = y0 + 1, x1 = x0 + 1;
                    float ly = py - fy, lx = px - fx;
                    float wy0 = ((y0 >= 0) & (y0 < Hin)) ? (1.f - ly) * mm : 0.f;
                    float wy1 = ((y1 >= 0) & (y1 < Hin)) ? ly * mm : 0.f;
                    float wx0 = ((x0 >= 0) & (x0 < Win)) ? (1.f - lx) : 0.f;
                    float wx1 = ((x1 >= 0) & (x1 < Win)) ? lx : 0.f;
                    int xL = min(max(x0, 0), Win - 2);
                    float wL = (x0 == xL ? wx0 : 0.f) + (x1 == xL ? wx1 : 0.f);
                    float wR = (x0 == xL + 1 ? wx0 : 0.f) + (x1 == xL + 1 ? wx1 : 0.f);
                    int yT = min(max(y0, 0), Hin - 1);
                    int yB = min(max(y1, 0), Hin - 1);
                    ad[pp][u] = make_int2(yT * Win + xL, (yB - yT) * Win);
                    wq[pp][u] = make_float4(wy0 * wL, wy0 * wR, wy1 * wL, wy1 * wR);
                }
            }
            for (int c = 0; c < NC; c++) {
                int slot = c & 3;
                if (c >= 4) {
                    MBAR_WAIT(sb + OFF_MBAR + 32 + slot*8, (*phE >> slot) & 1);
                    *phE ^= 1u << slot;
                }
                uint32_t sB0 = sb + OFF_B + (uint32_t)((slot*2 + 0) * 8192);
                uint32_t sB1 = sb + OFF_B + (uint32_t)((slot*2 + 1) * 8192);
#pragma unroll
                for (int q = 0; q < 4; q++) {
                    const float* plane = xb + (size_t)(c * 4 + q) * HWin;
#pragma unroll
                    for (int pp = 0; pp < 2; pp++) {
                        const float* p0 = plane + ad[pp][0].x;
                        const float* p1 = plane + ad[pp][1].x;
                        float v0 = wq[pp][0].x*p0[0] + wq[pp][0].y*p0[1]
                                 + wq[pp][0].z*p0[ad[pp][0].y] + wq[pp][0].w*p0[ad[pp][0].y+1];
                        float v1 = wq[pp][1].x*p1[0] + wq[pp][1].y*p1[1]
                                 + wq[pp][1].z*p1[ad[pp][1].y] + wq[pp][1].w*p1[ad[pp][1].y+1];
                        __nv_bfloat162 hh = __floats2bfloat162_rn(v0, v1);
                        float l0 = v0 - __bfloat162float(hh.x);
                        float l1 = v1 - __bfloat162float(hh.y);
                        __nv_bfloat162 ll = __floats2bfloat162_rn(l0, l1);
                        uint32_t so = rowb + (((uint32_t)(q * 32 + (g + pp*4) * 4)) ^ xorv);
                        *(uint32_t*)(size_t)(sB0 + so - sb + (size_t)smem) = *(uint32_t*)&hh;
                        *(uint32_t*)(size_t)(sB1 + so - sb + (size_t)smem) = *(uint32_t*)&ll;
                    }
                }
                MBAR_ARRIVE(sb + OFF_MBAR + slot*8);
            }
        } else {
            for (int c = 0; c < NC; c++) {
                int slot = c & 3;
                if (c >= 4) {
                    MBAR_WAIT(sb + OFF_MBAR + 32 + slot*8, (*phE >> slot) & 1);
                    *phE ^= 1u << slot;
                }
                int hw = hw0 + pxT;
                int h = hw / WOUT, w_ = hw - h * WOUT;
                int k0 = c * KC + g * 16;
                float r16[16];
#pragma unroll
                for (int t = 0; t < 16; t++) {
                    int k = k0 + t;
                    int ci = k / 9, jj = k - ci * 9;
                    int y  = h + jj / 3 - 1;
                    int xx = w_ + (jj - (jj / 3) * 3) - 1;
                    r16[t] = (y >= 0 && y < Hin && xx >= 0 && xx < Win)
                         ? __ldcg(&xb[(size_t)ci * HWin + y * Win + xx]) : 0.f;
                }
                char* pB0 = smem + OFF_B + (slot*2 + 0) * 8192;
                char* pB1 = smem + OFF_B + (slot*2 + 1) * 8192;
#pragma unroll
                for (int q = 0; q < 8; q++) {
                    __nv_bfloat162 hh = __floats2bfloat162_rn(r16[q*2], r16[q*2+1]);
                    float l0 = r16[q*2]   - __bfloat162float(hh.x);
                    float l1 = r16[q*2+1] - __bfloat162float(hh.y);
                    __nv_bfloat162 ll = __floats2bfloat162_rn(l0, l1);
                    uint32_t so = rowb + (((uint32_t)(g * 32 + q * 4)) ^ xorv);
                    *(uint32_t*)(pB0 + so) = *(uint32_t*)&hh;
                    *(uint32_t*)(pB1 + so) = *(uint32_t*)&ll;
                }
                MBAR_ARRIVE(sb + OFF_MBAR + slot*8);
            }
        }
    } else {
        // ================= CONSUMER (warps 0-7) =================
        const int wid = tid >> 5, lid = tid & 31;
        const int wm = wid & 3, wn = wid >> 2;        // 4m x 2n
        const int m0w = wm * (MT * 16);
        const int n0w = wn * 32;

        float acc[MT][4][4];
#pragma unroll
        for (int i = 0; i < MT; i++)
#pragma unroll
            for (int j = 0; j < 4; j++)
#pragma unroll
                for (int q = 0; q < 4; q++) acc[i][j][q] = 0.f;

        const uint32_t aOff = (uint32_t)((m0w + (lid & 15)) * 128 + (lid >> 4) * 16);
        const uint32_t bOff = (uint32_t)((n0w + (lid & 7) + ((lid >> 4) & 1) * 8) * 128 + ((lid >> 3) & 1) * 16);

        auto issueA = [&](int c) {
            uint32_t mb = sb + OFF_MBAR + 64 + (c & 1) * 8;
            asm volatile("fence.proxy.async.shared::cta;" ::: "memory");
            MBAR_EXPECT_TX(mb, (uint32_t)(2 * ABUF));
            BULK_G2S(sb + (uint32_t)(((c&1)*2 + 0) * ABUF),
                     wblk + (size_t)(c*2 + 0) * ABUF, (uint32_t)ABUF, mb);
            BULK_G2S(sb + (uint32_t)(((c&1)*2 + 1) * ABUF),
                     wblk + (size_t)(c*2 + 1) * ABUF, (uint32_t)ABUF, mb);
        };
        if (tid == 0) { issueA(0); if (NC > 1) issueA(1); }

        for (int c = 0; c < NC; c++) {
            const int buf = c & 1;
            const int slot = c & 3;
            MBAR_WAIT(sb + OFF_MBAR + 64 + buf*8, (*phA >> buf) & 1);
            *phA ^= 1u << buf;
            MBAR_WAIT(sb + OFF_MBAR + slot*8, (*phF >> slot) & 1);
            *phF ^= 1u << slot;

            const uint32_t sAh = sb + (uint32_t)((buf*2 + 0) * ABUF);
            const uint32_t sAl = sb + (uint32_t)((buf*2 + 1) * ABUF);
            const uint32_t sBh = sb + OFF_B + (uint32_t)((slot*2 + 0) * 8192);
            const uint32_t sBl = sb + OFF_B + (uint32_t)((slot*2 + 1) * 8192);

#pragma unroll
            for (int ks = 0; ks < 4; ks++) {
                uint32_t bh[8], bl[8];
                ldsm4(bh,     sBh + sw128(bOff + (uint32_t)(ks * 32)));
                ldsm4(bh + 4, sBh + sw128(bOff + 2048 + (uint32_t)(ks * 32)));
                ldsm4(bl,     sBl + sw128(bOff + (uint32_t)(ks * 32)));
                ldsm4(bl + 4, sBl + sw128(bOff + 2048 + (uint32_t)(ks * 32)));
#pragma unroll
                for (int i = 0; i < MT; i++) {
                    uint32_t ah[4], al[4];
                    ldsm4(ah, sAh + sw128(aOff + (uint32_t)(i * 2048 + ks * 32)));
                    ldsm4(al, sAl + sw128(aOff + (uint32_t)(i * 2048 + ks * 32)));
#pragma unroll
                    for (int jn = 0; jn < 4; jn++) {
                        int u = jn >> 1, sel = (jn & 1) * 2;
                        mma16816(acc[i][jn], ah, bh[u*4 + sel], bh[u*4 + sel + 1]);
                        mma16816(acc[i][jn], ah, bl[u*4 + sel], bl[u*4 + sel + 1]);
                        mma16816(acc[i][jn], al, bh[u*4 + sel], bh[u*4 + sel + 1]);
                    }
                }
            }
            asm volatile("bar.sync 1, 256;" ::: "memory");
            if (c + 4 < NC) MBAR_ARRIVE(sb + OFF_MBAR + 32 + slot*8);
            if (tid == 0 && c + 2 < NC) issueA(c + 2);
        }

        // ---- epilogue (consumers only) ----
#pragma unroll
        for (int i = 0; i < MT; i++) {
            int row0 = m0w + i * 16 + (lid >> 2);
#pragma unroll
            for (int half = 0; half < 2; half++) {
                int co = row0 + half * 8;
                if (co >= Cout) continue;
                float bv = bias[co];
#pragma unroll
                for (int jn = 0; jn < 4; jn++) {
                    float v0 = acc[i][jn][half * 2 + 0] + bv;
                    float v1 = acc[i][jn][half * 2 + 1] + bv;
                    if (EPI == 3) {
                        int cb = co * 64 + n0w + (lid & 3) * 2 + jn * 8;
                        som[cb] = v0; som[cb + 1] = v1;
                    } else {
                        size_t o = ((size_t)b * Cout + co) * HWOUT + hw0 + n0w + (lid & 3) * 2 + jn * 8;
                        if (EPI == 1) {
                            float2 s = __ldcg((const float2*)(epi_src + o));
                            v0 = fmaxf(v0, 0.f) + s.x; v1 = fmaxf(v1, 0.f) + s.y;
                        } else if (EPI == 2) {
                            float2 s = __ldcg((const float2*)(epi_src + o));
                            v0 += s.x; v1 += s.y;
                        }
                        *(float2*)(out + o) = make_float2(v0, v1);
                    }
                }
            }
        }
    }
}

__global__ void __launch_bounds__(NTHREADS)
dcnfpn_persist(const float* __restrict__ f0, const float* __restrict__ f1,
               const float* __restrict__ f2,
               const float* cw0, const float* cb0, const float* cw1, const float* cb1,
               const float* dw0, const float* db0, const float* dw1, const float* db1,
               const float* rw, const float* rb, float* __restrict__ out)
{
    extern __shared__ __align__(1024) char smem[];
    const int bx = blockIdx.x;
    const int tid = threadIdx.x;
    const int gtid = bx * NTHREADS + tid;
    const int GT = GRID * NTHREADS;
    const uint32_t sb = smem_u32(smem);

    if (tid == 0) {
#pragma unroll
        for (int s = 0; s < 4; s++) {
            MBAR_INIT(sb + OFF_MBAR + s*8, 256);        // fullB
            MBAR_INIT(sb + OFF_MBAR + 32 + s*8, 256);   // emptyB
        }
        MBAR_INIT(sb + OFF_MBAR + 64, 1);               // fullA[0]
        MBAR_INIT(sb + OFF_MBAR + 72, 1);               // fullA[1]
    }

    // ---- prep: weights fp32 -> bf16 hi/lo into pre-swizzled smem images ----
    {
        const float* dsrc[2] = {dw0, dw1};
        for (int l = 0; l < 2; l++) {
            char* base = (char*)g_wdef + (size_t)l * 2 * ND * 2;
            for (int i = gtid; i < ND; i += GT) {
                int r = i >> 12, k = i & 4095;
                int c = k >> 6, j = (k >> 3) & 7, t = k & 7;
                float v = dsrc[l][i];
                __nv_bfloat16 hbf = __float2bfloat16(v);
                __nv_bfloat16 lbf = __float2bfloat16(v - __bfloat162float(hbf));
                uint32_t off = (uint32_t)((c * 2) * 32768) + sw128((uint32_t)(r*128 + j*16)) + t*2;
                *(__nv_bfloat16*)(base + off)         = hbf;
                *(__nv_bfloat16*)(base + off + 32768) = lbf;
            }
        }
        const float* csrc[2] = {cw0, cw1};
        for (int l = 0; l < 2; l++) {
            char* base = (char*)g_wcom + (size_t)l * 2 * NCOM * 2;
            for (int i = gtid; i < NCOM; i += GT) {
                int r = i / KCONV, k = i - r * KCONV;
                int c = k >> 6, j = (k >> 3) & 7, t = k & 7;
                float v = (r < 48) ? csrc[l][i] : 0.f;
                __nv_bfloat16 hbf = __float2bfloat16(v);
                __nv_bfloat16 lbf = __float2bfloat16(v - __bfloat162float(hbf));
                uint32_t off = (uint32_t)((c * 2) * 8192) + sw128((uint32_t)(r*128 + j*16)) + t*2;
                *(__nv_bfloat16*)(base + off)        = hbf;
                *(__nv_bfloat16*)(base + off + 8192) = lbf;
            }
        }
        {
            char* base = (char*)g_wres;
            for (int i = gtid; i < NRES; i += GT) {
                int r = i / KCONV, k = i - r * KCONV;
                int c = k >> 6, j = (k >> 3) & 7, t = k & 7;
                float v = rw[i];
                __nv_bfloat16 hbf = __float2bfloat16(v);
                __nv_bfloat16 lbf = __float2bfloat16(v - __bfloat162float(hbf));
                uint32_t off = (uint32_t)((c * 2) * 32768) + sw128((uint32_t)(r*128 + j*16)) + t*2;
                *(__nv_bfloat16*)(base + off)         = hbf;
                *(__nv_bfloat16*)(base + off + 32768) = lbf;
            }
        }
        const float4* s4 = (const float4*)f2;
        float4* d4 = (float4*)g_f;
        for (int i = gtid; i < BATCH*CIN*HWOUT/4; i += GT) d4[i] = s4[i];
    }
    grid_bar(0);

    float* som = (float*)(smem + OFF_OM);
    const float* feats[2] = {f1, f0};
    const float* cb[2] = {cb0, cb1};
    const float* db[2] = {db0, db1};
    const int Hins[2] = {80, 160};
    const int strides[2] = {2, 4};
    const int pads[2] = {1, 3};
    const int dils[2] = {1, 3};

    uint32_t phF = 0, phE = 0, phA = 0;

    int slot = 1;
    for (int rep = 0; rep < 2; rep++) {
        for (int l = 0; l < 2; l++) {
            stage_gemm<0,3,1>(smem, bx, g_f, 40, 40,
                (const char*)g_wcom + (size_t)l*2*NCOM*2,
                cb[l], som, nullptr, nullptr, 48, KCONV, 1, 1, 1, &phF, &phE, &phA);
            stage_gemm<1,1,4>(smem, bx, feats[l], Hins[l], Hins[l],
                (const char*)g_wdef + (size_t)l*2*ND*2,
                db[l], som, g_f, g_f, 256, KDEF, strides[l], pads[l], dils[l], &phF, &phE, &phA);
            grid_bar(slot++);
        }
    }
    stage_gemm<0,2,4>(smem, bx, g_f, 40, 40,
        (const char*)g_wres, rb, nullptr, f2, out, 256, KCONV, 1, 1, 1, &phF, &phE, &phA);
}

extern "C" void kernel_launch(void* const* d_in, const int* in_sizes, int n_in,
                              void* d_out, int out_size)
{
    const float* f0 = (const float*)d_in[0];
    const float* f1 = (const float*)d_in[1];
    const float* f2 = (const float*)d_in[2];

    cudaFuncSetAttribute(dcnfpn_persist, cudaFuncAttributeMaxDynamicSharedMemorySize, SMEM_TOTAL);

    dcnfpn_persist<<<GRID, NTHREADS, SMEM_TOTAL>>>(
        f0, f1, f2,
        (const float*)d_in[3], (const float*)d_in[4],
        (const float*)d_in[5], (const float*)d_in[6],
        (const float*)d_in[7], (const float*)d_in[8],
        (const float*)d_in[9], (const float*)d_in[10],
        (const float*)d_in[11], (const float*)d_in[12],
        (float*)d_out);
}